// round 1
// baseline (speedup 1.0000x reference)
#include <cuda_runtime.h>
#include <math.h>

// Problem constants
#define HDIM   512
#define BDIM   512
#define GDIM   2048   // 4*H
#define NSTEPS 30

// Scratch (device globals — no allocation allowed)
__device__ __align__(16) float g_gates[BDIM * GDIM];          // 4 MB
__device__ __align__(16) float g_h[2 * BDIM * HDIM];          // 2 MB
__device__ __align__(16) float g_c[2 * BDIM * HDIM];          // 2 MB

// ---------------- GEMM: C[m,n] = sum_k A1[m,k]W1[n,k] + sum_k A2[m,k]W2[n,k] + b1[n] + b2[n]
// A1,A2: [512,512] row-major.  W1,W2: [2048,512] row-major.  C: [512,2048].
#define BM 64
#define BN 128
#define BK 16
#define TM 4
#define TN 8
// 256 threads: tx = tid&15 (n), ty = tid>>4 (m)

__global__ __launch_bounds__(256, 2) void gemm_gates(
    const float* __restrict__ A1, const float* __restrict__ W1,
    const float* __restrict__ A2, const float* __restrict__ W2,
    const float* __restrict__ b1, const float* __restrict__ b2,
    float* __restrict__ C)
{
    __shared__ float As[BK][BM];
    __shared__ float Ws[BK][BN];

    const int tid = threadIdx.x;
    const int tx = tid & 15;
    const int ty = tid >> 4;
    const int m0 = blockIdx.y * BM;
    const int n0 = blockIdx.x * BN;

    // A tile load mapping: 64x16 floats = 1 float4/thread
    const int a_row = tid >> 2;           // 0..63
    const int a_k4  = (tid & 3) * 4;      // 0,4,8,12
    // W tile load mapping: 128x16 floats = 2 float4/thread
    // f4idx = tid*2+j -> row = idx>>2 (0..127), k4 = (idx&3)*4

    float acc[TM][TN];
#pragma unroll
    for (int i = 0; i < TM; i++)
#pragma unroll
        for (int j = 0; j < TN; j++) acc[i][j] = 0.f;

    float4 a_reg;
    float4 w_reg[2];

    // prologue: tile 0 (k=0 -> A1/W1)
    a_reg = *(const float4*)(A1 + (m0 + a_row) * HDIM + a_k4);
#pragma unroll
    for (int j = 0; j < 2; j++) {
        int idx = tid * 2 + j;
        int wrow = idx >> 2, wk4 = (idx & 3) * 4;
        w_reg[j] = *(const float4*)(W1 + (n0 + wrow) * HDIM + wk4);
    }

    const int NIT = (2 * HDIM) / BK;   // 64 iterations over fused K=1024
    for (int it = 0; it < NIT; it++) {
        // commit prefetched regs to smem (transposed: [k][m]/[k][n])
        As[a_k4 + 0][a_row] = a_reg.x;
        As[a_k4 + 1][a_row] = a_reg.y;
        As[a_k4 + 2][a_row] = a_reg.z;
        As[a_k4 + 3][a_row] = a_reg.w;
#pragma unroll
        for (int j = 0; j < 2; j++) {
            int idx = tid * 2 + j;
            int wrow = idx >> 2, wk4 = (idx & 3) * 4;
            Ws[wk4 + 0][wrow] = w_reg[j].x;
            Ws[wk4 + 1][wrow] = w_reg[j].y;
            Ws[wk4 + 2][wrow] = w_reg[j].z;
            Ws[wk4 + 3][wrow] = w_reg[j].w;
        }
        __syncthreads();

        // prefetch next tile while computing this one
        if (it + 1 < NIT) {
            int kk = (it + 1) * BK;
            const float* Ap; const float* Wp; int kb;
            if (kk < HDIM) { Ap = A1; Wp = W1; kb = kk; }
            else           { Ap = A2; Wp = W2; kb = kk - HDIM; }
            a_reg = *(const float4*)(Ap + (m0 + a_row) * HDIM + kb + a_k4);
#pragma unroll
            for (int j = 0; j < 2; j++) {
                int idx = tid * 2 + j;
                int wrow = idx >> 2, wk4 = (idx & 3) * 4;
                w_reg[j] = *(const float4*)(Wp + (n0 + wrow) * HDIM + kb + wk4);
            }
        }

#pragma unroll
        for (int kq = 0; kq < BK; kq++) {
            float a[TM], w[TN];
#pragma unroll
            for (int i = 0; i < TM; i++) a[i] = As[kq][ty * TM + i];
#pragma unroll
            for (int j = 0; j < TN; j++) w[j] = Ws[kq][tx + j * 16];
#pragma unroll
            for (int i = 0; i < TM; i++)
#pragma unroll
                for (int j = 0; j < TN; j++)
                    acc[i][j] = fmaf(a[i], w[j], acc[i][j]);
        }
        __syncthreads();
    }

    // epilogue: add biases, write gates
#pragma unroll
    for (int j = 0; j < TN; j++) {
        int n = n0 + tx + j * 16;
        float bias = b1[n] + b2[n];
#pragma unroll
        for (int i = 0; i < TM; i++) {
            int m = m0 + ty * TM + i;
            C[m * GDIM + n] = acc[i][j] + bias;
        }
    }
}

// ---------------- LSTM cell elementwise
__device__ __forceinline__ float sigmoidf_(float x) { return 1.f / (1.f + __expf(-x)); }

__global__ __launch_bounds__(256) void lstm_cell(
    const float* __restrict__ gates,
    float* __restrict__ h, float* __restrict__ c,
    float* __restrict__ ys)
{
    int idx = blockIdx.x * blockDim.x + threadIdx.x;
    if (idx >= BDIM * HDIM) return;
    int m = idx >> 9;        // / 512
    int j = idx & 511;
    const float* gr = gates + m * GDIM;
    float gi = sigmoidf_(gr[j]);
    float gf = sigmoidf_(gr[j + HDIM]);
    float gg = tanhf(gr[j + 2 * HDIM]);
    float go = sigmoidf_(gr[j + 3 * HDIM]);
    float cn = gf * c[idx] + gi * gg;
    float hn = go * tanhf(cn);
    c[idx] = cn;
    h[idx] = hn;
    if (ys) ys[idx] = hn;
}

__global__ void zero_state() {
    int idx = blockIdx.x * blockDim.x + threadIdx.x;
    if (idx < 2 * BDIM * HDIM) { g_h[idx] = 0.f; g_c[idx] = 0.f; }
}

// ---------------- launch
extern "C" void kernel_launch(void* const* d_in, const int* in_sizes, int n_in,
                              void* d_out, int out_size)
{
    const float* x    = (const float*)d_in[0];
    const float* W_ih = (const float*)d_in[1];
    const float* W_hh = (const float*)d_in[2];
    const float* b_ih = (const float*)d_in[3];
    const float* b_hh = (const float*)d_in[4];
    float* out = (float*)d_out;

    float *gates, *hbuf, *cbuf;
    cudaGetSymbolAddress((void**)&gates, g_gates);
    cudaGetSymbolAddress((void**)&hbuf,  g_h);
    cudaGetSymbolAddress((void**)&cbuf,  g_c);

    zero_state<<<(2 * BDIM * HDIM + 255) / 256, 256>>>();

    dim3 ggrid(GDIM / BN, BDIM / BM);                    // (16, 8) = 128 blocks
    int cellBlocks = (BDIM * HDIM + 255) / 256;          // 1024 blocks

    const size_t BH  = (size_t)BDIM * HDIM;
    const size_t WSZ = (size_t)GDIM * HDIM;

    for (int t = 0; t < NSTEPS; t++) {
        int xt = (t == NSTEPS - 1) ? NSTEPS - 2 : t;     // source bug: step 29 reuses x[28]
        const float* xp = x + (size_t)xt * BH;

        // layer 0: gates = x_t @ Wih0^T + h0 @ Whh0^T + b
        {
            size_t wo = ((size_t)t * 2 + 0);
            gemm_gates<<<ggrid, 256>>>(xp, W_ih + wo * WSZ,
                                       hbuf, W_hh + wo * WSZ,
                                       b_ih + wo * GDIM, b_hh + wo * GDIM, gates);
            lstm_cell<<<cellBlocks, 256>>>(gates, hbuf, cbuf, nullptr);
        }
        // layer 1: gates = h0_t @ Wih1^T + h1 @ Whh1^T + b ; y_t = h1_t
        {
            size_t wo = ((size_t)t * 2 + 1);
            gemm_gates<<<ggrid, 256>>>(hbuf, W_ih + wo * WSZ,
                                       hbuf + BH, W_hh + wo * WSZ,
                                       b_ih + wo * GDIM, b_hh + wo * GDIM, gates);
            lstm_cell<<<cellBlocks, 256>>>(gates, hbuf + BH, cbuf + BH,
                                           out + (size_t)t * BH);
        }
    }

    // final h, c sections
    cudaMemcpyAsync(out + (size_t)NSTEPS * BH,       hbuf, 2 * BH * sizeof(float),
                    cudaMemcpyDeviceToDevice);
    cudaMemcpyAsync(out + (size_t)(NSTEPS + 2) * BH, cbuf, 2 * BH * sizeof(float),
                    cudaMemcpyDeviceToDevice);
}

// round 3
// speedup vs baseline: 2.2319x; 2.2319x over previous
#include <cuda_runtime.h>
#include <cstdint>
#include <math.h>

#define HDIM   512
#define BDIM   512
#define GDIM   2048
#define NSTEPS 30
#define BH     (BDIM * HDIM)

// h ping-pong: [parity][layer][B][H]; c in-place per layer
__device__ __align__(1024) float g_h[2 * 2 * BH];   // 4 MB
__device__ __align__(1024) float g_c[2 * BH];       // 2 MB

// ---------------- helpers ----------------
__device__ __forceinline__ uint32_t smem_u32(const void* p) {
    uint32_t a;
    asm("{ .reg .u64 t; cvta.to.shared.u64 t, %1; cvt.u32.u64 %0, t; }" : "=r"(a) : "l"(p));
    return a;
}

#define CP_ASYNC16(dst_u32, src_ptr) \
    asm volatile("cp.async.cg.shared.global [%0], [%1], 16;" \
                 :: "r"(dst_u32), "l"(src_ptr) : "memory")
#define CP_COMMIT() asm volatile("cp.async.commit_group;" ::: "memory")
#define CP_WAIT2()  asm volatile("cp.async.wait_group 2;" ::: "memory")

__device__ __forceinline__ uint32_t f2tf32(float f) {
    uint32_t r;
    asm("cvt.rna.tf32.f32 %0, %1;" : "=r"(r) : "f"(f));
    return r;
}

__device__ __forceinline__ void mma_tf32(float* d,
                                         uint32_t a0, uint32_t a1, uint32_t a2, uint32_t a3,
                                         uint32_t b0, uint32_t b1) {
    asm volatile(
        "mma.sync.aligned.m16n8k8.row.col.f32.tf32.tf32.f32 "
        "{%0,%1,%2,%3}, {%4,%5,%6,%7}, {%8,%9}, {%0,%1,%2,%3};"
        : "+f"(d[0]), "+f"(d[1]), "+f"(d[2]), "+f"(d[3])
        : "r"(a0), "r"(a1), "r"(a2), "r"(a3), "r"(b0), "r"(b1));
}

__device__ __forceinline__ float sigmoidf_(float x) { return 1.0f / (1.0f + __expf(-x)); }

// ---------------- smem layout (floats) ----------------
// per stage: As[64][20] = 1280, Ws[128][20] = 2560 -> 3840
#define SSTRIDE 3840
#define WOFF    1280
#define NSTAGE  4
#define BIASOFF (NSTAGE * SSTRIDE)          // 15360
#define SMEM_FLOATS (BIASOFF + 128)         // 15488
#define SMEM_BYTES  (SMEM_FLOATS * 4)       // 61952
#define NIT 64                              // K = 1024 / 16

// issue cp.async loads for pipeline stage of iteration `it`
__device__ __forceinline__ void issue_stage(uint32_t sb, int it,
                                            const float* A1, const float* A2,
                                            const float* W1, const float* W2,
                                            int m0, int j0, int tid) {
    const int s = it & (NSTAGE - 1);
    const int k0 = it * 16;
    const float* Ap = (k0 < 512) ? A1 : A2;
    const float* Wp = (k0 < 512) ? W1 : W2;
    const int kk = k0 & 511;
    const uint32_t as = sb + (uint32_t)(s * SSTRIDE) * 4u;
    const uint32_t ws = as + WOFF * 4u;
    // A tile: 64 rows x 16 k -> 256 float4, one per thread
    {
        int m = tid >> 2, c = tid & 3;
        CP_ASYNC16(as + (uint32_t)(m * 20 + c * 4) * 4u,
                   Ap + (size_t)(m0 + m) * HDIM + kk + c * 4);
    }
    // W tile: 128 interleaved rows (n_local = jj*4+g) x 16 k -> 512 float4, two per thread
#pragma unroll
    for (int u = 0; u < 2; u++) {
        int idx = tid + u * 256;
        int r = idx >> 2, c = idx & 3;
        int grow = (r & 3) * 512 + j0 + (r >> 2);     // g*512 + j0 + jj
        CP_ASYNC16(ws + (uint32_t)(r * 20 + c * 4) * 4u,
                   Wp + (size_t)grow * HDIM + kk + c * 4);
    }
}

__global__ __launch_bounds__(256) void lstm_mma(
    const float* __restrict__ A1, const float* __restrict__ A2,
    const float* __restrict__ W1, const float* __restrict__ W2,
    const float* __restrict__ b1, const float* __restrict__ b2,
    float* __restrict__ c_ptr, float* __restrict__ h_out, float* __restrict__ y_out)
{
    extern __shared__ float sm[];
    const uint32_t sb = smem_u32(sm);
    const int tid = threadIdx.x;
    const int lane = tid & 31;
    const int wid = tid >> 5;
    const int wm = wid & 3;          // M group (16 rows)
    const int wn = wid >> 2;         // N group (64 n_local)
    const int m0 = blockIdx.y * 64;
    const int j0 = blockIdx.x * 32;

    // preload bias: smb[g*32+jj] = b1 + b2
    if (tid < 128) {
        int g = tid >> 5, jj = tid & 31;
        sm[BIASOFF + tid] = b1[g * 512 + j0 + jj] + b2[g * 512 + j0 + jj];
    }

    float acc[8][4];
#pragma unroll
    for (int n = 0; n < 8; n++)
#pragma unroll
        for (int e = 0; e < 4; e++) acc[n][e] = 0.f;

    // pipeline prologue
    issue_stage(sb, 0, A1, A2, W1, W2, m0, j0, tid); CP_COMMIT();
    issue_stage(sb, 1, A1, A2, W1, W2, m0, j0, tid); CP_COMMIT();
    issue_stage(sb, 2, A1, A2, W1, W2, m0, j0, tid); CP_COMMIT();

    const int arow = wm * 16 + (lane >> 2);
    const int kb = lane & 3;

    for (int it = 0; it < NIT; it++) {
        CP_WAIT2();
        __syncthreads();
        if (it + 3 < NIT) issue_stage(sb, it + 3, A1, A2, W1, W2, m0, j0, tid);
        CP_COMMIT();   // empty groups at tail keep wait_group accounting correct

        const float* as = sm + (it & (NSTAGE - 1)) * SSTRIDE;
        const float* ws = as + WOFF;
#pragma unroll
        for (int ks = 0; ks < 16; ks += 8) {
            uint32_t a0 = f2tf32(as[arow * 20 + ks + kb]);
            uint32_t a1 = f2tf32(as[(arow + 8) * 20 + ks + kb]);
            uint32_t a2 = f2tf32(as[arow * 20 + ks + kb + 4]);
            uint32_t a3 = f2tf32(as[(arow + 8) * 20 + ks + kb + 4]);
#pragma unroll
            for (int nt = 0; nt < 8; nt++) {
                int brow = wn * 64 + nt * 8 + (lane >> 2);
                uint32_t bb0 = f2tf32(ws[brow * 20 + ks + kb]);
                uint32_t bb1 = f2tf32(ws[brow * 20 + ks + kb + 4]);
                mma_tf32(acc[nt], a0, a1, a2, a3, bb0, bb1);
            }
        }
    }

    // ---------------- fused LSTM cell epilogue ----------------
    __syncthreads();
    float* smc = sm;                 // [64][33] c tile
    float* smh = sm + SSTRIDE;       // [64][33] h tile
    const float* smb = sm + BIASOFF;

    // coalesced c_old load
    for (int i = tid; i < 64 * 32; i += 256) {
        int r = i >> 5, jj = i & 31;
        smc[r * 33 + jj] = c_ptr[(size_t)(m0 + r) * HDIM + j0 + jj];
    }
    __syncthreads();

    const int rbase = wm * 16 + (lane >> 2) + ((lane & 1) << 3);
    const bool ev = !(lane & 1);
#pragma unroll
    for (int nt = 0; nt < 8; nt++) {
        // lane pair (lane, lane^1) holds same (jj): even = (i,f), odd = (g,o)
        float x0 = __shfl_xor_sync(0xFFFFFFFFu, acc[nt][0], 1);
        float x1 = __shfl_xor_sync(0xFFFFFFFFu, acc[nt][1], 1);
        float x2 = __shfl_xor_sync(0xFFFFFFFFu, acc[nt][2], 1);
        float x3 = __shfl_xor_sync(0xFFFFFFFFu, acc[nt][3], 1);
        int jj = wn * 16 + nt * 2 + ((lane >> 1) & 1);
        float vi = (ev ? acc[nt][0] : x2) + smb[jj];
        float vf = (ev ? acc[nt][1] : x3) + smb[32 + jj];
        float vg = (ev ? x0 : acc[nt][2]) + smb[64 + jj];
        float vo = (ev ? x1 : acc[nt][3]) + smb[96 + jj];
        float ii = sigmoidf_(vi);
        float ff = sigmoidf_(vf);
        float gg = tanhf(vg);
        float oo = sigmoidf_(vo);
        float cn = ff * smc[rbase * 33 + jj] + ii * gg;
        float hn = oo * tanhf(cn);
        smc[rbase * 33 + jj] = cn;
        smh[rbase * 33 + jj] = hn;
    }
    __syncthreads();

    // coalesced stores
    for (int i = tid; i < 64 * 32; i += 256) {
        int r = i >> 5, jj = i & 31;
        size_t gidx = (size_t)(m0 + r) * HDIM + j0 + jj;
        float hv = smh[r * 33 + jj];
        c_ptr[gidx] = smc[r * 33 + jj];
        h_out[gidx] = hv;
        if (y_out) y_out[gidx] = hv;
    }
}

// zero h parity-1 planes (read at t=0) and all of c
__global__ void zero_state() {
    int i = blockIdx.x * 256 + threadIdx.x;
    if (i < 2 * BH) { g_h[2 * BH + i] = 0.f; g_c[i] = 0.f; }
}

// ---------------- host ----------------
extern "C" void kernel_launch(void* const* d_in, const int* in_sizes, int n_in,
                              void* d_out, int out_size)
{
    const float* x    = (const float*)d_in[0];
    const float* W_ih = (const float*)d_in[1];
    const float* W_hh = (const float*)d_in[2];
    const float* b_ih = (const float*)d_in[3];
    const float* b_hh = (const float*)d_in[4];
    float* out = (float*)d_out;

    float *hbuf, *cbuf;
    cudaGetSymbolAddress((void**)&hbuf, g_h);
    cudaGetSymbolAddress((void**)&cbuf, g_c);

    cudaFuncSetAttribute(lstm_mma, cudaFuncAttributeMaxDynamicSharedMemorySize, SMEM_BYTES);

    zero_state<<<(2 * BH + 255) / 256, 256>>>();

    const size_t WSZ = (size_t)GDIM * HDIM;
    dim3 grid(16, 8);   // 16 j-blocks x 8 m-blocks = 128 CTAs

    for (int t = 0; t < NSTEPS; t++) {
        int xt = (t < NSTEPS - 1) ? t : NSTEPS - 2;   // source bug: step 29 reuses x[28]
        int wp = t & 1, rp = wp ^ 1;

        // layer 0: A1 = x[xt], A2 = h(rp,0) -> h(wp,0), c0
        {
            size_t wo = (size_t)(t * 2 + 0);
            lstm_mma<<<grid, 256, SMEM_BYTES>>>(
                x + (size_t)xt * BH, hbuf + (size_t)(rp * 2 + 0) * BH,
                W_ih + wo * WSZ, W_hh + wo * WSZ,
                b_ih + wo * GDIM, b_hh + wo * GDIM,
                cbuf, hbuf + (size_t)(wp * 2 + 0) * BH, nullptr);
        }
        // layer 1: A1 = h(wp,0), A2 = h(rp,1) -> h(wp,1), c1, y[t]
        {
            size_t wo = (size_t)(t * 2 + 1);
            lstm_mma<<<grid, 256, SMEM_BYTES>>>(
                hbuf + (size_t)(wp * 2 + 0) * BH, hbuf + (size_t)(rp * 2 + 1) * BH,
                W_ih + wo * WSZ, W_hh + wo * WSZ,
                b_ih + wo * GDIM, b_hh + wo * GDIM,
                cbuf + BH, hbuf + (size_t)(wp * 2 + 1) * BH, out + (size_t)t * BH);
        }
    }

    // final h (t=29 -> wp=1 -> planes 2,3), then c
    cudaMemcpyAsync(out + (size_t)NSTEPS * BH, hbuf + (size_t)2 * BH,
                    2 * BH * sizeof(float), cudaMemcpyDeviceToDevice);
    cudaMemcpyAsync(out + (size_t)(NSTEPS + 2) * BH, cbuf,
                    2 * BH * sizeof(float), cudaMemcpyDeviceToDevice);
}

// round 4
// speedup vs baseline: 5.5273x; 2.4765x over previous
#include <cuda_runtime.h>
#include <cuda_fp16.h>
#include <cstdint>
#include <math.h>

#define HDIM   512
#define BDIM   512
#define GDIM   2048
#define NSTEPS 30
#define BH     (BDIM * HDIM)
#define BH2    (BDIM * 256)          // half2 per [512,512] plane
#define WPL2   (2048 * 256)          // half2 per [2048,512] weight plane

// fp16 k-permuted copies (pre-converted each launch)
__device__ __align__(1024) __half2 g_w16ih[60 * WPL2];   // 125.8 MB
__device__ __align__(1024) __half2 g_w16hh[60 * WPL2];   // 125.8 MB
__device__ __align__(1024) __half2 g_x16[NSTEPS * BH2];  // 15.7 MB
__device__ __align__(1024) __half2 g_h16[4 * BH2];       // [parity][layer], 2 MB
__device__ __align__(1024) float   g_c[2 * BH];          // 2 MB

// ---------------- helpers ----------------
__device__ __forceinline__ uint32_t smem_u32(const void* p) {
    uint32_t a;
    asm("{ .reg .u64 t; cvta.to.shared.u64 t, %1; cvt.u32.u64 %0, t; }" : "=r"(a) : "l"(p));
    return a;
}
#define CP_ASYNC16(dst_u32, src_ptr) \
    asm volatile("cp.async.cg.shared.global [%0], [%1], 16;" \
                 :: "r"(dst_u32), "l"(src_ptr) : "memory")
#define CP_COMMIT() asm volatile("cp.async.commit_group;" ::: "memory")
#define CP_WAIT2()  asm volatile("cp.async.wait_group 2;" ::: "memory")

__device__ __forceinline__ void mma_f16(float* d,
                                        uint32_t a0, uint32_t a1, uint32_t a2, uint32_t a3,
                                        uint32_t b0, uint32_t b1) {
    asm volatile(
        "mma.sync.aligned.m16n8k16.row.col.f32.f16.f16.f32 "
        "{%0,%1,%2,%3}, {%4,%5,%6,%7}, {%8,%9}, {%0,%1,%2,%3};"
        : "+f"(d[0]), "+f"(d[1]), "+f"(d[2]), "+f"(d[3])
        : "r"(a0), "r"(a1), "r"(a2), "r"(a3), "r"(b0), "r"(b1));
}
__device__ __forceinline__ float sigmoidf_(float x) { return 1.0f / (1.0f + __expf(-x)); }

// ---------------- smem layout (bytes) ----------------
// stage: A 64x32 half = 4KB, W 128x32 half = 8KB -> 12288 B; 4 stages = 49152
#define STAGE_B   12288
#define BIAS_OFF  49152
#define SMEM_BYTES (BIAS_OFF + 512)
#define NIT 32   // K = 1024 / 32

struct Job {
    const __half2* A1; const __half2* A2;   // [512][256]
    const __half2* W1; const __half2* W2;   // [2048][256]
    const float* b1;   const float* b2;
    float* c; __half2* h16; float* y; float* h32;
};

__device__ __forceinline__ void issue_stage(uint32_t sb, int it, const Job& j,
                                            int m0, int j0, int tid) {
    const int s = it & 3;
    const __half2* Ap = (it < 16) ? j.A1 : j.A2;
    const __half2* Wp = (it < 16) ? j.W1 : j.W2;
    const int kk = (it & 15) << 4;              // half2 offset in row
    const uint32_t as = sb + s * STAGE_B;
    const uint32_t ws = as + 4096;
    {   // A: 64 rows x 4 chunks = 256 tasks
        int row = tid >> 2, u = tid & 3;
        CP_ASYNC16(as + (row << 6) + (u << 4),
                   Ap + (size_t)(m0 + row) * 256 + kk + u * 4);
    }
#pragma unroll
    for (int t2 = 0; t2 < 2; t2++) {            // W: 128 rows x 4 chunks = 512 tasks
        int idx = tid + t2 * 256;
        int r = idx >> 2, u = idx & 3;
        int grow = (r & 3) * 512 + j0 + (r >> 2);   // n_local -> g*512 + j0 + jj
        CP_ASYNC16(ws + (r << 6) + (u << 4),
                   Wp + (size_t)grow * 256 + kk + u * 4);
    }
}

__global__ __launch_bounds__(256, 2) void lstm_pair(Job jobA, Job jobB) {
    extern __shared__ char smem[];
    const uint32_t sb = smem_u32(smem);
    const Job j = (blockIdx.z == 0) ? jobA : jobB;

    const int tid  = threadIdx.x;
    const int lane = tid & 31;
    const int wid  = tid >> 5;
    const int wm = wid & 3;          // 4 m-groups x 16 rows
    const int wn = wid >> 1 & ~0;    // placeholder (computed below)
    const int wng = wid >> 2;        // 2 n-groups x 64 n_local
    const int r4 = lane >> 2;
    const int u  = lane & 3;
    const int m0 = blockIdx.y * 64;
    const int j0 = blockIdx.x * 32;
    (void)wn;

    float* smb = (float*)(smem + BIAS_OFF);
    if (tid < 128) {
        int g = tid >> 5, jj = tid & 31;
        smb[tid] = j.b1[g * 512 + j0 + jj] + j.b2[g * 512 + j0 + jj];
    }

    float acc[8][4];
#pragma unroll
    for (int n = 0; n < 8; n++)
#pragma unroll
        for (int e = 0; e < 4; e++) acc[n][e] = 0.f;

    issue_stage(sb, 0, j, m0, j0, tid); CP_COMMIT();
    issue_stage(sb, 1, j, m0, j0, tid); CP_COMMIT();
    issue_stage(sb, 2, j, m0, j0, tid); CP_COMMIT();

    const int a_row0 = (wm * 16 + r4) << 6;
    const int a_row1 = (wm * 16 + r4 + 8) << 6;
    const int b_base = ((wng * 64 + r4) << 6) + 4096;
    const int uoff = u << 4;

    for (int it = 0; it < NIT; it++) {
        CP_WAIT2();
        __syncthreads();
        if (it + 3 < NIT) issue_stage(sb, it + 3, j, m0, j0, tid);
        CP_COMMIT();

        const char* st = smem + (it & 3) * STAGE_B;
        uint4 alo = *(const uint4*)(st + a_row0 + uoff);
        uint4 ahi = *(const uint4*)(st + a_row1 + uoff);
#pragma unroll
        for (int nt = 0; nt < 8; nt++) {
            uint4 bb = *(const uint4*)(st + b_base + (nt << 9) + uoff);
            mma_f16(acc[nt], alo.x, ahi.x, alo.y, ahi.y, bb.x, bb.y);   // k 0..15
            mma_f16(acc[nt], alo.z, ahi.z, alo.w, ahi.w, bb.z, bb.w);   // k 16..31
        }
    }

    // ---------------- fused LSTM cell epilogue ----------------
    __syncthreads();
    float* smc = (float*)smem;              // [64][33]
    float* smh = (float*)(smem + 8448);     // [64][33]

    for (int i = tid; i < 64 * 32; i += 256) {
        int r = i >> 5, jj = i & 31;
        smc[r * 33 + jj] = j.c[(size_t)(m0 + r) * HDIM + j0 + jj];
    }
    __syncthreads();

    const bool evn = !(u & 1);
    const int row = wm * 16 + r4 + (evn ? 0 : 8);
#pragma unroll
    for (int nt = 0; nt < 8; nt++) {
        float x0 = __shfl_xor_sync(0xFFFFFFFFu, acc[nt][0], 1);
        float x1 = __shfl_xor_sync(0xFFFFFFFFu, acc[nt][1], 1);
        float x2 = __shfl_xor_sync(0xFFFFFFFFu, acc[nt][2], 1);
        float x3 = __shfl_xor_sync(0xFFFFFFFFu, acc[nt][3], 1);
        int jj = wng * 16 + nt * 2 + (u >> 1);
        float vi = (evn ? acc[nt][0] : x2) + smb[jj];
        float vf = (evn ? acc[nt][1] : x3) + smb[32 + jj];
        float vg = (evn ? x0 : acc[nt][2]) + smb[64 + jj];
        float vo = (evn ? x1 : acc[nt][3]) + smb[96 + jj];
        float ii = sigmoidf_(vi);
        float ff = sigmoidf_(vf);
        float gg = tanhf(vg);
        float oo = sigmoidf_(vo);
        float cn = ff * smc[row * 33 + jj] + ii * gg;
        float hn = oo * tanhf(cn);
        smc[row * 33 + jj] = cn;
        smh[row * 33 + jj] = hn;
    }
    __syncthreads();

    for (int i = tid; i < 64 * 32; i += 256) {
        int r = i >> 5, jj = i & 31;
        size_t g = (size_t)(m0 + r) * HDIM + j0 + jj;
        j.c[g] = smc[r * 33 + jj];
        float hv = smh[r * 33 + jj];
        if (j.y)   j.y[g]   = hv;
        if (j.h32) j.h32[g] = hv;
    }
    // h16: k-permuted half2 layout
    for (int i = tid; i < 64 * 16; i += 256) {
        int r = i >> 4, q = i & 15;
        int p = (q & 3) * 4 + (q >> 2);
        j.h16[(size_t)(m0 + r) * 256 + (j0 >> 1) + p] =
            __floats2half2_rn(smh[r * 33 + 2 * q], smh[r * 33 + 2 * q + 1]);
    }
}

// fp32 -> fp16 with k-permutation within 32-element blocks (rows of 512)
__global__ __launch_bounds__(256) void conv_half(const float* __restrict__ src,
                                                 __half2* __restrict__ dst, int n_half2) {
    int e = blockIdx.x * 256 + threadIdx.x;
    if (e >= n_half2) return;
    int row = e >> 8;
    int qr = e & 255;
    int blk = qr >> 4, qb = qr & 15;
    int p = (qb & 3) * 4 + (qb >> 2);
    float2 v = ((const float2*)src)[e];
    dst[((size_t)row << 8) + (blk << 4) + p] = __floats2half2_rn(v.x, v.y);
}

__global__ void zero_state() {
    int i = blockIdx.x * 256 + threadIdx.x;
    if (i < 2 * BH2) g_h16[2 * BH2 + i] = __floats2half2_rn(0.f, 0.f);  // parity-1 planes
    if (i < 2 * BH)  g_c[i] = 0.f;
}

// ---------------- host ----------------
extern "C" void kernel_launch(void* const* d_in, const int* in_sizes, int n_in,
                              void* d_out, int out_size)
{
    const float* x    = (const float*)d_in[0];
    const float* W_ih = (const float*)d_in[1];
    const float* W_hh = (const float*)d_in[2];
    const float* b_ih = (const float*)d_in[3];
    const float* b_hh = (const float*)d_in[4];
    float* out = (float*)d_out;

    __half2 *w16ih, *w16hh, *x16, *h16;
    float* cbuf;
    cudaGetSymbolAddress((void**)&w16ih, g_w16ih);
    cudaGetSymbolAddress((void**)&w16hh, g_w16hh);
    cudaGetSymbolAddress((void**)&x16,   g_x16);
    cudaGetSymbolAddress((void**)&h16,   g_h16);
    cudaGetSymbolAddress((void**)&cbuf,  g_c);

    cudaFuncSetAttribute(lstm_pair, cudaFuncAttributeMaxDynamicSharedMemorySize, SMEM_BYTES);

    const int nW = 60 * WPL2;          // 31.5M half2
    const int nX = NSTEPS * BH2;
    conv_half<<<(nW + 255) / 256, 256>>>(W_ih, w16ih, nW);
    conv_half<<<(nW + 255) / 256, 256>>>(W_hh, w16hh, nW);
    conv_half<<<(nX + 255) / 256, 256>>>(x, x16, nX);
    zero_state<<<(2 * BH + 255) / 256, 256>>>();

    auto mkL0 = [&](int t) -> Job {
        int xt = (t < NSTEPS - 1) ? t : NSTEPS - 2;    // source bug: step 29 reuses x[28]
        int wp = t & 1, rp = wp ^ 1;
        Job jb;
        jb.A1 = x16 + (size_t)xt * BH2;
        jb.A2 = h16 + (size_t)(rp * 2 + 0) * BH2;
        jb.W1 = w16ih + (size_t)(t * 2 + 0) * WPL2;
        jb.W2 = w16hh + (size_t)(t * 2 + 0) * WPL2;
        jb.b1 = b_ih + (size_t)(t * 2 + 0) * GDIM;
        jb.b2 = b_hh + (size_t)(t * 2 + 0) * GDIM;
        jb.c  = cbuf;
        jb.h16 = h16 + (size_t)(wp * 2 + 0) * BH2;
        jb.y = nullptr;
        jb.h32 = (t == NSTEPS - 1) ? (out + (size_t)NSTEPS * BH) : nullptr;
        return jb;
    };
    auto mkL1 = [&](int t) -> Job {
        int wp = t & 1, rp = wp ^ 1;
        Job jb;
        jb.A1 = h16 + (size_t)(wp * 2 + 0) * BH2;
        jb.A2 = h16 + (size_t)(rp * 2 + 1) * BH2;
        jb.W1 = w16ih + (size_t)(t * 2 + 1) * WPL2;
        jb.W2 = w16hh + (size_t)(t * 2 + 1) * WPL2;
        jb.b1 = b_ih + (size_t)(t * 2 + 1) * GDIM;
        jb.b2 = b_hh + (size_t)(t * 2 + 1) * GDIM;
        jb.c  = cbuf + BH;
        jb.h16 = h16 + (size_t)(wp * 2 + 1) * BH2;
        jb.y = out + (size_t)t * BH;
        jb.h32 = (t == NSTEPS - 1) ? (out + (size_t)(NSTEPS + 1) * BH) : nullptr;
        return jb;
    };

    // C(0): L0(0); C(k)=L0(k)+L1(k-1); C(30): L1(29)
    {
        Job a = mkL0(0);
        lstm_pair<<<dim3(16, 8, 1), 256, SMEM_BYTES>>>(a, a);
    }
    for (int k = 1; k < NSTEPS; k++) {
        Job a = mkL0(k), b = mkL1(k - 1);
        lstm_pair<<<dim3(16, 8, 2), 256, SMEM_BYTES>>>(a, b);
    }
    {
        Job a = mkL1(NSTEPS - 1);
        lstm_pair<<<dim3(16, 8, 1), 256, SMEM_BYTES>>>(a, a);
    }

    // c planes -> output tail
    cudaMemcpyAsync(out + (size_t)(NSTEPS + 2) * BH, cbuf,
                    2 * BH * sizeof(float), cudaMemcpyDeviceToDevice);
}